// round 1
// baseline (speedup 1.0000x reference)
#include <cuda_runtime.h>
#include <cuda_bf16.h>

#define H 512
#define W 512
#define OW 510            // number of windows per dim (512 - 3 + 1)
#define PLANE (H * W)

__device__ double g_accum;

__global__ void ml_zero_kernel() { g_accum = 0.0; }

__global__ void ml_final_kernel(float* out) { out[0] = (float)g_accum; }

__global__ __launch_bounds__(256)
void ml_main_kernel(const float* __restrict__ T, const float* __restrict__ V)
{
    const int c = blockIdx.x * blockDim.x + threadIdx.x;  // window col 0..509
    const int r = blockIdx.y;                             // window row 0..509

    float contrib = 0.0f;
    if (c < OW) {
        // 24 accumulators over the 9 window pixels
        float sT0 = 0.f, sT1 = 0.f, sT2 = 0.f;
        float s00 = 0.f, s01 = 0.f, s02 = 0.f, s11 = 0.f, s12 = 0.f, s22 = 0.f;
        float sV0 = 0.f, sV1 = 0.f, sV2 = 0.f;
        float q0 = 0.f, q1 = 0.f, q2 = 0.f;
        float m00 = 0.f, m01 = 0.f, m02 = 0.f;   // m[d][ch] = sum T_d * V_ch
        float m10 = 0.f, m11 = 0.f, m12 = 0.f;
        float m20 = 0.f, m21 = 0.f, m22 = 0.f;

        #pragma unroll
        for (int dr = 0; dr < 3; dr++) {
            const int base = (r + dr) * W + c;
            #pragma unroll
            for (int dc = 0; dc < 3; dc++) {
                const float t0 = __ldg(T + 0 * PLANE + base + dc);
                const float t1 = __ldg(T + 1 * PLANE + base + dc);
                const float t2 = __ldg(T + 2 * PLANE + base + dc);
                const float v0 = __ldg(V + 0 * PLANE + base + dc);
                const float v1 = __ldg(V + 1 * PLANE + base + dc);
                const float v2 = __ldg(V + 2 * PLANE + base + dc);

                sT0 += t0; sT1 += t1; sT2 += t2;
                s00 += t0 * t0; s01 += t0 * t1; s02 += t0 * t2;
                s11 += t1 * t1; s12 += t1 * t2; s22 += t2 * t2;

                sV0 += v0; sV1 += v1; sV2 += v2;
                q0 += v0 * v0; q1 += v1 * v1; q2 += v2 * v2;

                m00 += t0 * v0; m01 += t0 * v1; m02 += t0 * v2;
                m10 += t1 * v0; m11 += t1 * v1; m12 += t1 * v2;
                m20 += t2 * v0; m21 += t2 * v1; m22 += t2 * v2;
            }
        }

        const float inv9 = 1.0f / 9.0f;
        const float eps9 = 1e-7f * inv9;

        const float mu0 = sT0 * inv9, mu1 = sT1 * inv9, mu2 = sT2 * inv9;

        const float a00 = s00 * inv9 - mu0 * mu0 + eps9;
        const float a01 = s01 * inv9 - mu0 * mu1;
        const float a02 = s02 * inv9 - mu0 * mu2;
        const float a11 = s11 * inv9 - mu1 * mu1 + eps9;
        const float a12 = s12 * inv9 - mu1 * mu2;
        const float a22 = s22 * inv9 - mu2 * mu2 + eps9;

        // symmetric 3x3 inverse via cofactors
        const float c00 = a11 * a22 - a12 * a12;
        const float c01 = a02 * a12 - a01 * a22;
        const float c02 = a01 * a12 - a02 * a11;
        const float c11 = a00 * a22 - a02 * a02;
        const float c12 = a01 * a02 - a00 * a12;
        const float c22 = a00 * a11 - a01 * a01;
        const float det = a00 * c00 + a01 * c01 + a02 * c02;
        const float rdet = 1.0f / det;
        const float i00 = c00 * rdet, i01 = c01 * rdet, i02 = c02 * rdet;
        const float i11 = c11 * rdet, i12 = c12 * rdet, i22 = c22 * rdet;

        // channel 0
        {
            const float u0 = m00 - mu0 * sV0;
            const float u1 = m10 - mu1 * sV0;
            const float u2 = m20 - mu2 * sV0;
            const float quad = i00 * u0 * u0 + i11 * u1 * u1 + i22 * u2 * u2
                             + 2.f * (i01 * u0 * u1 + i02 * u0 * u2 + i12 * u1 * u2);
            contrib += q0 - inv9 * (sV0 * sV0 + quad);
        }
        // channel 1
        {
            const float u0 = m01 - mu0 * sV1;
            const float u1 = m11 - mu1 * sV1;
            const float u2 = m21 - mu2 * sV1;
            const float quad = i00 * u0 * u0 + i11 * u1 * u1 + i22 * u2 * u2
                             + 2.f * (i01 * u0 * u1 + i02 * u0 * u2 + i12 * u1 * u2);
            contrib += q1 - inv9 * (sV1 * sV1 + quad);
        }
        // channel 2
        {
            const float u0 = m02 - mu0 * sV2;
            const float u1 = m12 - mu1 * sV2;
            const float u2 = m22 - mu2 * sV2;
            const float quad = i00 * u0 * u0 + i11 * u1 * u1 + i22 * u2 * u2
                             + 2.f * (i01 * u0 * u1 + i02 * u0 * u2 + i12 * u1 * u2);
            contrib += q2 - inv9 * (sV2 * sV2 + quad);
        }
    }

    // block reduction (all 256 threads participate; inactive lanes hold 0)
    __shared__ float red[256];
    red[threadIdx.x] = contrib;
    __syncthreads();
    #pragma unroll
    for (int s = 128; s > 0; s >>= 1) {
        if (threadIdx.x < s) red[threadIdx.x] += red[threadIdx.x + s];
        __syncthreads();
    }
    if (threadIdx.x == 0) atomicAdd(&g_accum, (double)red[0]);
}

extern "C" void kernel_launch(void* const* d_in, const int* in_sizes, int n_in,
                              void* d_out, int out_size)
{
    const float* target = (const float*)d_in[0];
    const float* style  = (const float*)d_in[1];
    float* out = (float*)d_out;

    ml_zero_kernel<<<1, 1>>>();

    dim3 block(256, 1, 1);
    dim3 grid((OW + 255) / 256, OW, 1);
    ml_main_kernel<<<grid, block>>>(target, style);

    ml_final_kernel<<<1, 1>>>(out);
}